// round 4
// baseline (speedup 1.0000x reference)
#include <cuda_runtime.h>
#include <cuda_fp16.h>
#include <math.h>
#include <stdint.h>

// ContinuousRelativePositionalBias — Round 4:
//  * fp16 single-pass HMMA (error model validated in R3: ~3e-4 << 1e-3)
//  * persistent CTAs (148 x 512 threads), W2 loaded once per CTA
//  * 2-deep software pipeline: bias(t+2) | H1-gen(t+1) | GEMM(t), 2 barriers/tile

#define ID 512
#define JD 512
#define DD 128
#define TILE 128
#define NTHREADS 512
#define GRIDSZ 148
#define NTILES 8192

// XOR swizzle for 256B rows of fp16 (128 cols): 16B-chunk ^= (row & 7)
#define SWZ(row, chunk) ((unsigned)(row) * 256u + ((((unsigned)(chunk)) ^ ((unsigned)(row) & 7u)) << 4))

// smem byte offsets
#define OFF_W2    0         // 32KB fp16 W2 [k][n] swizzled
#define OFF_H1A   32768     // 32KB fp16 H1 buffer A
#define OFF_H1B   65536     // 32KB fp16 H1 buffer B
#define OFF_RED   98304     // 512 float4 = 8KB
#define OFF_BIASA 106496    // 3*128 floats
#define OFF_BIASB 108032
#define OFF_W1    109568    // 384 floats
#define OFF_B1    111104    // 128
#define OFF_B2    111616    // 128
#define OFF_W3    112128    // 512 floats [e][o]
#define OFF_B3    114176    // 4
#define SMEM_BYTES 114304

__device__ __align__(16) uint8_t g_w2h[32768];

// ---------------- prep: W2 -> fp16, swizzled row-major [k][n] ----------------
__global__ void prep_w2(const float* __restrict__ W2) {
    int idx = blockIdx.x * blockDim.x + threadIdx.x;
    if (idx >= DD * DD) return;
    int k = idx >> 7, n = idx & 127;
    unsigned byte = SWZ(k, n >> 3) + (unsigned)(n & 7) * 2u;
    *(uint16_t*)(g_w2h + byte) = __half_as_ushort(__float2half_rn(W2[idx]));
}

// ---------------- PTX helpers ----------------
__device__ __forceinline__ uint32_t smem_u32(const void* p) {
    uint32_t a;
    asm("{ .reg .u64 t; cvta.to.shared.u64 t, %1; cvt.u32.u64 %0, t; }" : "=r"(a) : "l"(p));
    return a;
}
__device__ __forceinline__ void ldsm_x4(uint32_t* r, uint32_t addr) {
    asm volatile("ldmatrix.sync.aligned.m8n8.x4.shared.b16 {%0,%1,%2,%3}, [%4];"
                 : "=r"(r[0]), "=r"(r[1]), "=r"(r[2]), "=r"(r[3]) : "r"(addr));
}
__device__ __forceinline__ void ldsm_x4t(uint32_t* r, uint32_t addr) {
    asm volatile("ldmatrix.sync.aligned.m8n8.x4.trans.shared.b16 {%0,%1,%2,%3}, [%4];"
                 : "=r"(r[0]), "=r"(r[1]), "=r"(r[2]), "=r"(r[3]) : "r"(addr));
}
__device__ __forceinline__ void mma_fp16(float* c, const uint32_t* a, uint32_t b0, uint32_t b1) {
    asm volatile("mma.sync.aligned.m16n8k16.row.col.f32.f16.f16.f32 "
                 "{%0,%1,%2,%3}, {%4,%5,%6,%7}, {%8,%9}, {%0,%1,%2,%3};"
                 : "+f"(c[0]), "+f"(c[1]), "+f"(c[2]), "+f"(c[3])
                 : "r"(a[0]), "r"(a[1]), "r"(a[2]), "r"(a[3]), "r"(b0), "r"(b1));
}
#define CP_ASYNC16(dst, src) \
    asm volatile("cp.async.cg.shared.global [%0], [%1], 16;" :: "r"(dst), "l"(src) : "memory")
#define CP_ASYNC_COMMIT() asm volatile("cp.async.commit_group;" ::: "memory")
#define CP_ASYNC_WAIT0()  asm volatile("cp.async.wait_group 0;" ::: "memory")

// ---------------- stage helpers ----------------
__device__ __forceinline__ void compute_bias(int tile, float* sB,
                                             const float* __restrict__ grid_q,
                                             const float* __restrict__ grid_kv, int tid) {
    if (tid < TILE) {
        const int jt = tile & 3;
        const int i  = (tile >> 2) & (ID - 1);
        const int b  = tile >> 11;
        const int j  = jt * TILE + tid;
        const float q0 = __ldg(grid_q + i * 3 + 0);
        const float q1 = __ldg(grid_q + i * 3 + 1);
        const float q2 = __ldg(grid_q + i * 3 + 2);
        const float p0 = q0 - grid_kv[(b * JD + j) * 3 + 0];
        const float p1 = q1 - grid_kv[(b * JD + j) * 3 + 1];
        const float p2 = q2 - grid_kv[(b * JD + j) * 3 + 2];
        sB[tid]       = copysignf(__logf(1.0f + fabsf(p0)), p0);
        sB[128 + tid] = copysignf(__logf(1.0f + fabsf(p1)), p1);
        sB[256 + tid] = copysignf(__logf(1.0f + fabsf(p2)), p2);
    }
}

__device__ __forceinline__ void gen_h1(const float* __restrict__ sB,
                                       const float* __restrict__ sW1,
                                       const float* __restrict__ sb1,
                                       char* hbuf, int tid) {
    const int p  = tid >> 2;       // point 0..127
    const int q4 = tid & 3;        // 32-col slice
    const float bs0 = sB[p];
    const float bs1 = sB[128 + p];
    const float bs2 = sB[256 + p];
    #pragma unroll
    for (int dd = 0; dd < 4; ++dd) {
        const int d0 = q4 * 32 + dd * 8;
        uint32_t hv[4];
        #pragma unroll
        for (int q = 0; q < 4; ++q) {
            const int d = d0 + 2 * q;
            float h0 = fmaxf(fmaf(bs0, sW1[d],     fmaf(bs1, sW1[DD + d],     fmaf(bs2, sW1[2*DD + d],     sb1[d]))),     0.0f);
            float h1 = fmaxf(fmaf(bs0, sW1[d + 1], fmaf(bs1, sW1[DD + d + 1], fmaf(bs2, sW1[2*DD + d + 1], sb1[d + 1]))), 0.0f);
            __half2 hh = __floats2half2_rn(h0, h1);
            hv[q] = *(uint32_t*)&hh;
        }
        *(uint4*)(hbuf + SWZ(p, d0 >> 3)) = make_uint4(hv[0], hv[1], hv[2], hv[3]);
    }
}

// ---------------- main persistent kernel ----------------
__global__ __launch_bounds__(NTHREADS, 1)
void crpb_kernel(const float* __restrict__ grid_q,
                 const float* __restrict__ grid_kv,
                 const float* __restrict__ W1, const float* __restrict__ b1,
                 const float* __restrict__ b2,
                 const float* __restrict__ W3, const float* __restrict__ b3,
                 float* __restrict__ out)
{
    extern __shared__ __align__(1024) char smem[];
    float* sW1   = (float*)(smem + OFF_W1);
    float* sb1   = (float*)(smem + OFF_B1);
    float* sb2   = (float*)(smem + OFF_B2);
    float* sW3   = (float*)(smem + OFF_W3);
    float* sb3   = (float*)(smem + OFF_B3);
    float* sBiasA = (float*)(smem + OFF_BIASA);
    float* sBiasB = (float*)(smem + OFF_BIASB);
    float4* red4 = (float4*)(smem + OFF_RED);

    const int tid  = threadIdx.x;
    const int lane = tid & 31;
    const int wid  = tid >> 5;

    // ---- one-time prologue ----
    for (int v = tid; v < 3 * DD; v += NTHREADS) sW1[v] = W1[v];
    for (int v = tid; v < DD; v += NTHREADS)     { sb1[v] = b1[v]; sb2[v] = b2[v]; }
    for (int v = tid; v < DD * 4; v += NTHREADS) sW3[v] = W3[v];
    if (tid < 4) sb3[tid] = b3[tid];
    {
        uint32_t dst = smem_u32(smem + OFF_W2) + tid * 16;
        const char* src = (const char*)g_w2h + tid * 16;
        #pragma unroll
        for (int it = 0; it < 4; ++it) CP_ASYNC16(dst + it * 8192, src + it * 8192);
        CP_ASYNC_COMMIT();
    }

    const int nt = (NTILES - blockIdx.x + GRIDSZ - 1) / GRIDSZ;
    #define TILE_AT(k) (blockIdx.x + (k) * GRIDSZ)

    compute_bias(TILE_AT(0), sBiasA, grid_q, grid_kv, tid);
    if (nt > 1) compute_bias(TILE_AT(1), sBiasB, grid_q, grid_kv, tid);
    CP_ASYNC_WAIT0();
    __syncthreads();
    gen_h1(sBiasA, sW1, sb1, smem + OFF_H1A, tid);
    __syncthreads();

    // GEMM per-lane invariants (warp tile 32M x 32N; 16 warps = 4M x 4N)
    const int wm = wid & 3;
    const int wn = wid >> 2;
    const int arow  = wm * 32 + (lane & 15);
    const unsigned axor  = lane & 7;
    const unsigned ahalf = lane >> 4;
    const int brow  = ((lane >> 3) & 1) * 8 + (lane & 7);
    const unsigned bsel  = lane >> 4;
    const int g  = lane >> 2;
    const int t4 = lane & 3;
    const uint32_t w2b = smem_u32(smem + OFF_W2);

    for (int k = 0; k < nt; ++k) {
        // pipeline stages for future tiles (no barrier before GEMM)
        if (k + 2 < nt)
            compute_bias(TILE_AT(k + 2), (k & 1) ? sBiasB : sBiasA, grid_q, grid_kv, tid);
        if (k + 1 < nt)
            gen_h1((k & 1) ? sBiasA : sBiasB, sW1, sb1,
                   smem + (((k + 1) & 1) ? OFF_H1B : OFF_H1A), tid);

        // ---- GEMM(t): H1[128,128] @ W2[128,128], fp16 -> f32 ----
        const uint32_t h1b = smem_u32(smem + ((k & 1) ? OFF_H1B : OFF_H1A));
        float acc[2][4][4];
        #pragma unroll
        for (int mt = 0; mt < 2; ++mt)
            #pragma unroll
            for (int n = 0; n < 4; ++n)
                #pragma unroll
                for (int c = 0; c < 4; ++c) acc[mt][n][c] = 0.0f;

        #pragma unroll
        for (int kc = 0; kc < 8; ++kc) {
            uint32_t A[2][4];
            const unsigned achunk = (((unsigned)(kc * 2) + ahalf) ^ axor) << 4;
            ldsm_x4(A[0], h1b + (unsigned)arow * 256u + achunk);
            ldsm_x4(A[1], h1b + (unsigned)(arow + 16) * 256u + achunk);
            #pragma unroll
            for (int nt2 = 0; nt2 < 2; ++nt2) {
                uint32_t B[4];
                const unsigned bchunk = (((unsigned)(wn * 4 + nt2 * 2) + bsel) ^ axor) << 4;
                ldsm_x4t(B, w2b + (unsigned)(kc * 16 + brow) * 256u + bchunk);
                mma_fp16(acc[0][nt2 * 2],     A[0], B[0], B[1]);
                mma_fp16(acc[0][nt2 * 2 + 1], A[0], B[2], B[3]);
                mma_fp16(acc[1][nt2 * 2],     A[1], B[0], B[1]);
                mma_fp16(acc[1][nt2 * 2 + 1], A[1], B[2], B[3]);
            }
        }

        // ---- epilogue: relu(H2+b2) @ W3 in registers ----
        float ov[2][2][4];
        #pragma unroll
        for (int mt = 0; mt < 2; ++mt)
            #pragma unroll
            for (int h = 0; h < 2; ++h)
                #pragma unroll
                for (int o = 0; o < 4; ++o) ov[mt][h][o] = 0.0f;

        #pragma unroll
        for (int n = 0; n < 4; ++n) {
            const int e0 = wn * 32 + n * 8 + 2 * t4;
            float2 b2v = *(const float2*)(sb2 + e0);
            float4 w30 = *(const float4*)(sW3 + e0 * 4);
            float4 w31 = *(const float4*)(sW3 + (e0 + 1) * 4);
            #pragma unroll
            for (int mt = 0; mt < 2; ++mt) {
                float h00 = fmaxf(acc[mt][n][0] + b2v.x, 0.0f);
                float h01 = fmaxf(acc[mt][n][1] + b2v.y, 0.0f);
                float h10 = fmaxf(acc[mt][n][2] + b2v.x, 0.0f);
                float h11 = fmaxf(acc[mt][n][3] + b2v.y, 0.0f);
                ov[mt][0][0] = fmaf(h00, w30.x, fmaf(h01, w31.x, ov[mt][0][0]));
                ov[mt][0][1] = fmaf(h00, w30.y, fmaf(h01, w31.y, ov[mt][0][1]));
                ov[mt][0][2] = fmaf(h00, w30.z, fmaf(h01, w31.z, ov[mt][0][2]));
                ov[mt][0][3] = fmaf(h00, w30.w, fmaf(h01, w31.w, ov[mt][0][3]));
                ov[mt][1][0] = fmaf(h10, w30.x, fmaf(h11, w31.x, ov[mt][1][0]));
                ov[mt][1][1] = fmaf(h10, w30.y, fmaf(h11, w31.y, ov[mt][1][1]));
                ov[mt][1][2] = fmaf(h10, w30.z, fmaf(h11, w31.z, ov[mt][1][2]));
                ov[mt][1][3] = fmaf(h10, w30.w, fmaf(h11, w31.w, ov[mt][1][3]));
            }
        }
        #pragma unroll
        for (int mt = 0; mt < 2; ++mt)
            #pragma unroll
            for (int h = 0; h < 2; ++h)
                #pragma unroll
                for (int o = 0; o < 4; ++o) {
                    float v = ov[mt][h][o];
                    v += __shfl_xor_sync(0xFFFFFFFF, v, 1);
                    v += __shfl_xor_sync(0xFFFFFFFF, v, 2);
                    ov[mt][h][o] = v;
                }
        if (t4 == 0) {
            #pragma unroll
            for (int mt = 0; mt < 2; ++mt)
                #pragma unroll
                for (int h = 0; h < 2; ++h)
                    red4[wn * 128 + wm * 32 + mt * 16 + h * 8 + g] =
                        make_float4(ov[mt][h][0], ov[mt][h][1], ov[mt][h][2], ov[mt][h][3]);
        }
        __syncthreads();

        if (tid < TILE) {
            const float4 r0 = red4[tid];
            const float4 r1 = red4[128 + tid];
            const float4 r2 = red4[256 + tid];
            const float4 r3 = red4[384 + tid];
            const int tile = TILE_AT(k);
            const int jt = tile & 3;
            const int i  = (tile >> 2) & (ID - 1);
            const int b  = tile >> 11;
            const long base = ((long)(b * 4) * ID + i) * JD + jt * TILE + tid;
            const long os   = (long)ID * JD;
            out[base]          = r0.x + r1.x + r2.x + r3.x + sb3[0];
            out[base + os]     = r0.y + r1.y + r2.y + r3.y + sb3[1];
            out[base + 2 * os] = r0.z + r1.z + r2.z + r3.z + sb3[2];
            out[base + 3 * os] = r0.w + r1.w + r2.w + r3.w + sb3[3];
        }
        __syncthreads();
    }
}

extern "C" void kernel_launch(void* const* d_in, const int* in_sizes, int n_in,
                              void* d_out, int out_size)
{
    const float* grid_q  = (const float*)d_in[0];
    const float* grid_kv = (const float*)d_in[1];
    const float* W1      = (const float*)d_in[2];
    const float* b1      = (const float*)d_in[3];
    const float* W2      = (const float*)d_in[4];
    const float* b2      = (const float*)d_in[5];
    const float* W3      = (const float*)d_in[6];
    const float* b3      = (const float*)d_in[7];
    float* out = (float*)d_out;

    prep_w2<<<DD * DD / 256, 256>>>(W2);

    cudaFuncSetAttribute(crpb_kernel,
                         cudaFuncAttributeMaxDynamicSharedMemorySize, SMEM_BYTES);
    crpb_kernel<<<GRIDSZ, NTHREADS, SMEM_BYTES>>>(
        grid_q, grid_kv, W1, b1, b2, W3, b3, out);
}

// round 5
// speedup vs baseline: 2.4206x; 2.4206x over previous
#include <cuda_runtime.h>
#include <cuda_fp16.h>
#include <math.h>
#include <stdint.h>

// ContinuousRelativePositionalBias — Round 5:
//  * fp16 single-pass HMMA, persistent CTAs (148 x 256 thr)
//  * NO transposed ldmatrix: W2^T stored [n][k] (col-major for row.col mma)
//  * big warp tiles: iter = 256 pts x 128 cols, 8 warps, warp tile 64x64
//    -> 4 MMA per ldsm.x4, ~128KB LDSM per 128-pt tile (2x less than R4)

#define ID 512
#define JD 512
#define DD 128
#define MROWS 256            // points per iteration (two j-tiles)
#define NTHREADS 256
#define GRIDSZ 148
#define NITER 4096           // 4 * 512 * 2

// XOR swizzle for 256B rows of fp16 (128 cols): 16B-chunk ^= (row & 7)
#define SWZ(row, chunk) ((unsigned)(row) * 256u + ((((unsigned)(chunk)) ^ ((unsigned)(row) & 7u)) << 4))

// smem byte offsets
#define OFF_W2    0          // 32KB fp16 W2^T [n][k] swizzled
#define OFF_H1A   32768      // 64KB fp16 H1 buffer A (256 x 128)
#define OFF_H1B   98304      // 64KB fp16 H1 buffer B
#define OFF_RED   163840     // 512 float4 = 8KB
#define OFF_BIASA 172032     // 3*256 floats = 3KB
#define OFF_BIASB 175104     // 3KB
#define OFF_W1    178176     // 384 floats
#define OFF_B1    179712     // 128
#define OFF_B2    180224     // 128
#define OFF_W3    180736     // 512 floats [e][o]
#define OFF_B3    182784     // 4
#define SMEM_BYTES 182912

__device__ __align__(16) uint8_t g_w2h[32768];

// ---------------- prep: W2 -> fp16 W2^T, [n][k] swizzled ----------------
__global__ void prep_w2(const float* __restrict__ W2) {
    int idx = blockIdx.x * blockDim.x + threadIdx.x;
    if (idx >= DD * DD) return;
    int n = idx >> 7, k = idx & 127;
    unsigned byte = SWZ(n, k >> 3) + (unsigned)(k & 7) * 2u;
    *(uint16_t*)(g_w2h + byte) = __half_as_ushort(__float2half_rn(W2[k * DD + n]));
}

// ---------------- PTX helpers ----------------
__device__ __forceinline__ uint32_t smem_u32(const void* p) {
    uint32_t a;
    asm("{ .reg .u64 t; cvta.to.shared.u64 t, %1; cvt.u32.u64 %0, t; }" : "=r"(a) : "l"(p));
    return a;
}
__device__ __forceinline__ void ldsm_x4(uint32_t* r, uint32_t addr) {
    asm volatile("ldmatrix.sync.aligned.m8n8.x4.shared.b16 {%0,%1,%2,%3}, [%4];"
                 : "=r"(r[0]), "=r"(r[1]), "=r"(r[2]), "=r"(r[3]) : "r"(addr));
}
__device__ __forceinline__ void mma_fp16(float* c, const uint32_t* a, uint32_t b0, uint32_t b1) {
    asm volatile("mma.sync.aligned.m16n8k16.row.col.f32.f16.f16.f32 "
                 "{%0,%1,%2,%3}, {%4,%5,%6,%7}, {%8,%9}, {%0,%1,%2,%3};"
                 : "+f"(c[0]), "+f"(c[1]), "+f"(c[2]), "+f"(c[3])
                 : "r"(a[0]), "r"(a[1]), "r"(a[2]), "r"(a[3]), "r"(b0), "r"(b1));
}
#define CP_ASYNC16(dst, src) \
    asm volatile("cp.async.cg.shared.global [%0], [%1], 16;" :: "r"(dst), "l"(src) : "memory")
#define CP_ASYNC_COMMIT() asm volatile("cp.async.commit_group;" ::: "memory")
#define CP_ASYNC_WAIT0()  asm volatile("cp.async.wait_group 0;" ::: "memory")

// ---------------- stage helpers ----------------
__device__ __forceinline__ void compute_bias(int it, float* sB,
                                             const float* __restrict__ grid_q,
                                             const float* __restrict__ grid_kv, int tid) {
    const int pair = it & 1;
    const int i    = (it >> 1) & (ID - 1);
    const int b    = it >> 10;
    const int j    = pair * MROWS + tid;
    const float q0 = __ldg(grid_q + i * 3 + 0);
    const float q1 = __ldg(grid_q + i * 3 + 1);
    const float q2 = __ldg(grid_q + i * 3 + 2);
    const float p0 = q0 - grid_kv[(b * JD + j) * 3 + 0];
    const float p1 = q1 - grid_kv[(b * JD + j) * 3 + 1];
    const float p2 = q2 - grid_kv[(b * JD + j) * 3 + 2];
    sB[tid]             = copysignf(__logf(1.0f + fabsf(p0)), p0);
    sB[MROWS + tid]     = copysignf(__logf(1.0f + fabsf(p1)), p1);
    sB[2 * MROWS + tid] = copysignf(__logf(1.0f + fabsf(p2)), p2);
}

__device__ __forceinline__ void gen_h1(const float* __restrict__ sB,
                                       const float* __restrict__ sW1,
                                       const float* __restrict__ sb1,
                                       char* hbuf, int tid) {
    const int p = tid;                       // one point per thread
    const float bs0 = sB[p];
    const float bs1 = sB[MROWS + p];
    const float bs2 = sB[2 * MROWS + p];
    #pragma unroll
    for (int dd = 0; dd < 16; ++dd) {        // 16 chunks of 8 cols
        const int d0 = dd * 8;
        uint32_t hv[4];
        #pragma unroll
        for (int q = 0; q < 4; ++q) {
            const int d = d0 + 2 * q;
            float h0 = fmaxf(fmaf(bs0, sW1[d],     fmaf(bs1, sW1[DD + d],     fmaf(bs2, sW1[2*DD + d],     sb1[d]))),     0.0f);
            float h1 = fmaxf(fmaf(bs0, sW1[d + 1], fmaf(bs1, sW1[DD + d + 1], fmaf(bs2, sW1[2*DD + d + 1], sb1[d + 1]))), 0.0f);
            __half2 hh = __floats2half2_rn(h0, h1);
            hv[q] = *(uint32_t*)&hh;
        }
        *(uint4*)(hbuf + SWZ(p, dd)) = make_uint4(hv[0], hv[1], hv[2], hv[3]);
    }
}

// ---------------- main persistent kernel ----------------
__global__ __launch_bounds__(NTHREADS, 1)
void crpb_kernel(const float* __restrict__ grid_q,
                 const float* __restrict__ grid_kv,
                 const float* __restrict__ W1, const float* __restrict__ b1,
                 const float* __restrict__ b2,
                 const float* __restrict__ W3, const float* __restrict__ b3,
                 float* __restrict__ out)
{
    extern __shared__ __align__(1024) char smem[];
    float* sW1    = (float*)(smem + OFF_W1);
    float* sb1    = (float*)(smem + OFF_B1);
    float* sb2    = (float*)(smem + OFF_B2);
    float* sW3    = (float*)(smem + OFF_W3);
    float* sb3    = (float*)(smem + OFF_B3);
    float* sBiasA = (float*)(smem + OFF_BIASA);
    float* sBiasB = (float*)(smem + OFF_BIASB);
    float4* red4  = (float4*)(smem + OFF_RED);

    const int tid  = threadIdx.x;
    const int lane = tid & 31;
    const int wid  = tid >> 5;

    // ---- one-time prologue ----
    for (int v = tid; v < 3 * DD; v += NTHREADS) sW1[v] = W1[v];
    for (int v = tid; v < DD; v += NTHREADS)     { sb1[v] = b1[v]; sb2[v] = b2[v]; }
    for (int v = tid; v < DD * 4; v += NTHREADS) sW3[v] = W3[v];
    if (tid < 4) sb3[tid] = b3[tid];
    {
        uint32_t dst = smem_u32(smem + OFF_W2) + tid * 16;
        const char* src = (const char*)g_w2h + tid * 16;
        #pragma unroll
        for (int it = 0; it < 8; ++it) CP_ASYNC16(dst + it * 4096, src + it * 4096);
        CP_ASYNC_COMMIT();
    }

    const int nt = (NITER - blockIdx.x + GRIDSZ - 1) / GRIDSZ;
    #define TILE_AT(k) (blockIdx.x + (k) * GRIDSZ)

    compute_bias(TILE_AT(0), sBiasA, grid_q, grid_kv, tid);
    if (nt > 1) compute_bias(TILE_AT(1), sBiasB, grid_q, grid_kv, tid);
    CP_ASYNC_WAIT0();
    __syncthreads();
    gen_h1(sBiasA, sW1, sb1, smem + OFF_H1A, tid);
    __syncthreads();

    // GEMM per-lane invariants: 8 warps = 4(wm) x 2(wn); warp tile 64M x 64N
    const int wm = wid & 3;
    const int wn = wid >> 2;
    const int arow = wm * 64 + (lane & 15);              // + mt*16
    const unsigned asel = lane >> 4;                     // k-chunk select
    const int brow = wn * 64 + (lane & 7) + ((lane >> 4) << 3);  // + ng*16
    const unsigned bsel = (lane >> 3) & 1;
    const int g  = lane >> 2;
    const int t4 = lane & 3;
    const uint32_t w2b = smem_u32(smem + OFF_W2);

    for (int k = 0; k < nt; ++k) {
        if (k + 2 < nt)
            compute_bias(TILE_AT(k + 2), (k & 1) ? sBiasB : sBiasA, grid_q, grid_kv, tid);
        if (k + 1 < nt)
            gen_h1((k & 1) ? sBiasA : sBiasB, sW1, sb1,
                   smem + (((k + 1) & 1) ? OFF_H1B : OFF_H1A), tid);

        // ---- GEMM: H1[256,128] @ W2[128,128] ----
        const uint32_t h1b = smem_u32(smem + ((k & 1) ? OFF_H1B : OFF_H1A));
        float acc[4][8][4];
        #pragma unroll
        for (int mt = 0; mt < 4; ++mt)
            #pragma unroll
            for (int n8 = 0; n8 < 8; ++n8)
                #pragma unroll
                for (int c = 0; c < 4; ++c) acc[mt][n8][c] = 0.0f;

        #pragma unroll
        for (int kc = 0; kc < 8; ++kc) {
            uint32_t A[4][4], Bf[4][4];
            #pragma unroll
            for (int mt = 0; mt < 4; ++mt)
                ldsm_x4(A[mt], h1b + SWZ(arow + mt * 16, kc * 2 + asel));
            #pragma unroll
            for (int ng = 0; ng < 4; ++ng)
                ldsm_x4(Bf[ng], w2b + SWZ(brow + ng * 16, kc * 2 + bsel));
            #pragma unroll
            for (int mt = 0; mt < 4; ++mt)
                #pragma unroll
                for (int ng = 0; ng < 4; ++ng) {
                    mma_fp16(acc[mt][2 * ng],     A[mt], Bf[ng][0], Bf[ng][1]);
                    mma_fp16(acc[mt][2 * ng + 1], A[mt], Bf[ng][2], Bf[ng][3]);
                }
        }

        // ---- epilogue: relu(H2+b2) @ W3, per mt to limit live regs ----
        #pragma unroll
        for (int mt = 0; mt < 4; ++mt) {
            float ov[2][4] = {{0,0,0,0},{0,0,0,0}};
            #pragma unroll
            for (int n8 = 0; n8 < 8; ++n8) {
                const int e0 = wn * 64 + n8 * 8 + 2 * t4;
                float2 b2v = *(const float2*)(sb2 + e0);
                float4 w30 = *(const float4*)(sW3 + e0 * 4);
                float4 w31 = *(const float4*)(sW3 + (e0 + 1) * 4);
                float h00 = fmaxf(acc[mt][n8][0] + b2v.x, 0.0f);
                float h01 = fmaxf(acc[mt][n8][1] + b2v.y, 0.0f);
                float h10 = fmaxf(acc[mt][n8][2] + b2v.x, 0.0f);
                float h11 = fmaxf(acc[mt][n8][3] + b2v.y, 0.0f);
                ov[0][0] = fmaf(h00, w30.x, fmaf(h01, w31.x, ov[0][0]));
                ov[0][1] = fmaf(h00, w30.y, fmaf(h01, w31.y, ov[0][1]));
                ov[0][2] = fmaf(h00, w30.z, fmaf(h01, w31.z, ov[0][2]));
                ov[0][3] = fmaf(h00, w30.w, fmaf(h01, w31.w, ov[0][3]));
                ov[1][0] = fmaf(h10, w30.x, fmaf(h11, w31.x, ov[1][0]));
                ov[1][1] = fmaf(h10, w30.y, fmaf(h11, w31.y, ov[1][1]));
                ov[1][2] = fmaf(h10, w30.z, fmaf(h11, w31.z, ov[1][2]));
                ov[1][3] = fmaf(h10, w30.w, fmaf(h11, w31.w, ov[1][3]));
            }
            #pragma unroll
            for (int h = 0; h < 2; ++h)
                #pragma unroll
                for (int o = 0; o < 4; ++o) {
                    float v = ov[h][o];
                    v += __shfl_xor_sync(0xFFFFFFFF, v, 1);
                    v += __shfl_xor_sync(0xFFFFFFFF, v, 2);
                    ov[h][o] = v;
                }
            if (t4 == 0) {
                red4[wn * 256 + wm * 64 + mt * 16 + g]     = make_float4(ov[0][0], ov[0][1], ov[0][2], ov[0][3]);
                red4[wn * 256 + wm * 64 + mt * 16 + 8 + g] = make_float4(ov[1][0], ov[1][1], ov[1][2], ov[1][3]);
            }
        }
        __syncthreads();

        {
            const float4 r0 = red4[tid];
            const float4 r1 = red4[256 + tid];
            const int it = TILE_AT(k);
            const int pair = it & 1;
            const int i    = (it >> 1) & (ID - 1);
            const int b    = it >> 10;
            const long base = ((long)(b * 4) * ID + i) * JD + pair * MROWS + tid;
            const long os   = (long)ID * JD;
            out[base]          = r0.x + r1.x + sb3[0];
            out[base + os]     = r0.y + r1.y + sb3[1];
            out[base + 2 * os] = r0.z + r1.z + sb3[2];
            out[base + 3 * os] = r0.w + r1.w + sb3[3];
        }
        __syncthreads();
    }
}

extern "C" void kernel_launch(void* const* d_in, const int* in_sizes, int n_in,
                              void* d_out, int out_size)
{
    const float* grid_q  = (const float*)d_in[0];
    const float* grid_kv = (const float*)d_in[1];
    const float* W1      = (const float*)d_in[2];
    const float* b1      = (const float*)d_in[3];
    const float* W2      = (const float*)d_in[4];
    const float* b2      = (const float*)d_in[5];
    const float* W3      = (const float*)d_in[6];
    const float* b3      = (const float*)d_in[7];
    float* out = (float*)d_out;

    prep_w2<<<DD * DD / 256, 256>>>(W2);

    cudaFuncSetAttribute(crpb_kernel,
                         cudaFuncAttributeMaxDynamicSharedMemorySize, SMEM_BYTES);
    crpb_kernel<<<GRIDSZ, NTHREADS, SMEM_BYTES>>>(
        grid_q, grid_kv, W1, b1, b2, W3, b3, out);
}